// round 16
// baseline (speedup 1.0000x reference)
#include <cuda_runtime.h>
#include <cuda_bf16.h>
#include <math.h>
#include <stdint.h>

// Problem constants (fixed shapes)
#define NROW   24576          // B*T
#define KDIM   512            // DIM
#define GV     640            // G*V
#define VNUM   320            // V per group
#define VD     128            // var_dim per group
#define NGROUP 2
#define OUT_MAIN (NROW * (NGROUP * VD))   // 24576*256
#define EPSQ   1e-7f
#define RCAP   4096           // refinement list capacity
#define REF_TAU 0.005f        // near-tie threshold for gumbel argmax

// Scratch (static device globals; no runtime allocation)
__device__ float g_logits[(size_t)NROW * GV];
__device__ float g_prob[GV];
__device__ float g_cnt[GV];
__device__ int   g_ref_cnt;
__device__ int   g_ref_list[RCAP];
__device__ __nv_bfloat16 g_xh[(size_t)NROW * KDIM];
__device__ __nv_bfloat16 g_xl[(size_t)NROW * KDIM];
__device__ __nv_bfloat16 g_wh[(size_t)GV * KDIM];
__device__ __nv_bfloat16 g_wl[(size_t)GV * KDIM];

// monotonic float<->uint key (no NaNs in this data)
__device__ __forceinline__ uint32_t fmono(float f) {
    uint32_t b = __float_as_uint(f);
    return (b & 0x80000000u) ? ~b : (b | 0x80000000u);
}
__device__ __forceinline__ float kinv(uint32_t k) {
    return __uint_as_float((k & 0x80000000u) ? (k ^ 0x80000000u) : ~k);
}

// ---------------------------------------------------------------------------
// Convert kernel: fp32 -> (bf16 hi, bf16 lo) split, 32B of input per thread,
// full 16B stores to each of hi/lo. Block 0 also zeroes the accumulators.
// ---------------------------------------------------------------------------
__device__ __forceinline__ void split4(float4 v, uint2& ph, uint2& pl) {
    __nv_bfloat16 h0 = __float2bfloat16_rn(v.x);
    __nv_bfloat16 h1 = __float2bfloat16_rn(v.y);
    __nv_bfloat16 h2 = __float2bfloat16_rn(v.z);
    __nv_bfloat16 h3 = __float2bfloat16_rn(v.w);
    __nv_bfloat16 l0 = __float2bfloat16_rn(v.x - __bfloat162float(h0));
    __nv_bfloat16 l1 = __float2bfloat16_rn(v.y - __bfloat162float(h1));
    __nv_bfloat16 l2 = __float2bfloat16_rn(v.z - __bfloat162float(h2));
    __nv_bfloat16 l3 = __float2bfloat16_rn(v.w - __bfloat162float(h3));
    ph.x = ((uint32_t)__bfloat16_as_ushort(h1) << 16) | __bfloat16_as_ushort(h0);
    ph.y = ((uint32_t)__bfloat16_as_ushort(h3) << 16) | __bfloat16_as_ushort(h2);
    pl.x = ((uint32_t)__bfloat16_as_ushort(l1) << 16) | __bfloat16_as_ushort(l0);
    pl.y = ((uint32_t)__bfloat16_as_ushort(l3) << 16) | __bfloat16_as_ushort(l2);
}

__device__ __forceinline__ void split8(const float4* src8, uint4& ph, uint4& pl) {
    uint2 ph0, pl0, ph1, pl1;
    split4(src8[0], ph0, pl0);
    split4(src8[1], ph1, pl1);
    ph = make_uint4(ph0.x, ph0.y, ph1.x, ph1.y);
    pl = make_uint4(pl0.x, pl0.y, pl1.x, pl1.y);
}

#define NX8 (NROW * KDIM / 8)   // 1572864 float4-pairs of x
#define NW8 (GV * KDIM / 8)     // 40960 float4-pairs of W

__global__ void convert_kernel(const float* __restrict__ x,
                               const float* __restrict__ W) {
    if (blockIdx.x == 0) {
        for (int t = threadIdx.x; t < GV; t += blockDim.x) {
            g_prob[t] = 0.0f; g_cnt[t] = 0.0f;
        }
        if (threadIdx.x == 0) g_ref_cnt = 0;
    }
    int i = blockIdx.x * blockDim.x + threadIdx.x;
    uint4 ph, pl;
    if (i < NX8) {
        split8((const float4*)x + 2 * (size_t)i, ph, pl);
        ((uint4*)g_xh)[i] = ph;
        ((uint4*)g_xl)[i] = pl;
    } else {
        int j = i - NX8;
        if (j < NW8) {
            split8((const float4*)W + 2 * (size_t)j, ph, pl);
            ((uint4*)g_wh)[j] = ph;
            ((uint4*)g_wl)[j] = pl;
        }
    }
}

// ---------------------------------------------------------------------------
// Kernel 1: 3-term split-bf16 GEMM via mma.sync.m16n8k16 + cp.async pipeline
// + ldmatrix.x4 (exact R13 mainloop — register knife-edge, do not add state).
// 128x128 tiles, k-tile 16, 2-stage, 256 threads (8 warps as 2m x 4n).
// Static 48KB smem. One __syncthreads per k-iteration.
// ---------------------------------------------------------------------------
#define KT    16
#define PITCH 24   // halves per row (48B; LDSM rows land on distinct bank groups)

#define MMA_BF16(d, a0, a1, a2, a3, b0, b1)                                  \
    asm volatile("mma.sync.aligned.m16n8k16.row.col.f32.bf16.bf16.f32 "      \
                 "{%0,%1,%2,%3}, {%4,%5,%6,%7}, {%8,%9}, {%0,%1,%2,%3};"     \
                 : "+f"(d[0]), "+f"(d[1]), "+f"(d[2]), "+f"(d[3])            \
                 : "r"(a0), "r"(a1), "r"(a2), "r"(a3), "r"(b0), "r"(b1))

#define CP_ASYNC16(saddr, gptr)                                              \
    asm volatile("cp.async.cg.shared.global [%0], [%1], 16;"                 \
                 :: "r"(saddr), "l"(gptr))

#define LDSM_X4(d0, d1, d2, d3, saddr)                                       \
    asm volatile("ldmatrix.sync.aligned.m8n8.x4.shared.b16 {%0,%1,%2,%3}, [%4];" \
                 : "=r"(d0), "=r"(d1), "=r"(d2), "=r"(d3) : "r"(saddr))

__global__ __launch_bounds__(256, 2)
void gemm3_kernel(const float* __restrict__ bias)
{
    // [stage][src][128*PITCH] : src 0=Ah 1=Al 2=Bh 3=Bl   (49152 bytes)
    __shared__ __nv_bfloat16 sm[2][4][128 * PITCH];

    const int tid  = threadIdx.x;
    const int bn   = blockIdx.x;          // 0..4
    const int bm   = blockIdx.y;          // 0..191
    const int warp = tid >> 5, lane = tid & 31;
    const int wm   = warp & 1;            // m offset 64*wm
    const int wn   = warp >> 1;           // n offset 32*wn
    const int qr   = lane >> 2, qc = lane & 3;

    // cp.async mapping: thread covers one 16B chunk per source per stage
    const int lrow = tid >> 1;            // 0..127
    const int lcol = (tid & 1) * 8;       // 0 or 8 (halves)
    const __nv_bfloat16* pAh = g_xh + (size_t)(bm * 128 + lrow) * KDIM + lcol;
    const __nv_bfloat16* pAl = g_xl + (size_t)(bm * 128 + lrow) * KDIM + lcol;
    const __nv_bfloat16* pBh = g_wh + (size_t)(bn * 128 + lrow) * KDIM + lcol;
    const __nv_bfloat16* pBl = g_wl + (size_t)(bn * 128 + lrow) * KDIM + lcol;

    uint32_t sbase = (uint32_t)__cvta_generic_to_shared(&sm[0][0][0]);
    const uint32_t soff = (uint32_t)(lrow * PITCH + lcol) * 2;
    const uint32_t stg  = 4u * 128u * PITCH * 2u;   // bytes per stage
    const uint32_t srcb = 128u * PITCH * 2u;        // bytes per source

    // ldmatrix lane addressing
    const int lg = lane >> 3;             // 0..3 (8-lane group)
    const int lr = lane & 7;              // row within group
    const uint32_t aRowB = (uint32_t)(wm * 64 + ((lg & 1) << 3) + lr) * (PITCH * 2)
                         + ((uint32_t)(lg >> 1) << 4);
    const uint32_t bRowB = (uint32_t)(wn * 32 + ((lg >> 1) << 3) + lr) * (PITCH * 2)
                         + ((uint32_t)(lg & 1) << 4);

    float acc[4][4][4];
#pragma unroll
    for (int mi = 0; mi < 4; mi++)
#pragma unroll
        for (int nj = 0; nj < 4; nj++)
#pragma unroll
            for (int r = 0; r < 4; r++) acc[mi][nj][r] = 0.0f;

    const int NK = KDIM / KT;   // 32

    // issue stage 0
    {
        const uint32_t d = sbase + soff;
        CP_ASYNC16(d + 0 * srcb, pAh);
        CP_ASYNC16(d + 1 * srcb, pAl);
        CP_ASYNC16(d + 2 * srcb, pBh);
        CP_ASYNC16(d + 3 * srcb, pBl);
        asm volatile("cp.async.commit_group;");
    }

    for (int kt = 0; kt < NK; kt++) {
        const int s = kt & 1;
        asm volatile("cp.async.wait_group 0;");
        __syncthreads();   // stage s visible; all warps done with stage s^1

        if (kt + 1 < NK) {
            const int ko = (kt + 1) * KT;
            const uint32_t d = sbase + (s ^ 1) * stg + soff;
            CP_ASYNC16(d + 0 * srcb, pAh + ko);
            CP_ASYNC16(d + 1 * srcb, pAl + ko);
            CP_ASYNC16(d + 2 * srcb, pBh + ko);
            CP_ASYNC16(d + 3 * srcb, pBl + ko);
            asm volatile("cp.async.commit_group;");
        }

        const uint32_t AhB = sbase + s * stg + 0 * srcb;
        const uint32_t AlB = sbase + s * stg + 1 * srcb;
        const uint32_t BhB = sbase + s * stg + 2 * srcb;
        const uint32_t BlB = sbase + s * stg + 3 * srcb;

        // B fragments for the whole k-tile (one KT=16 slice)
        uint32_t bh[4][2], bl[4][2];
#pragma unroll
        for (int p = 0; p < 2; p++) {
            const uint32_t ro = (uint32_t)(p * 16 * PITCH * 2);
            LDSM_X4(bh[2 * p][0], bh[2 * p][1], bh[2 * p + 1][0], bh[2 * p + 1][1],
                    BhB + bRowB + ro);
            LDSM_X4(bl[2 * p][0], bl[2 * p][1], bl[2 * p + 1][0], bl[2 * p + 1][1],
                    BlB + bRowB + ro);
        }
#pragma unroll
        for (int mi = 0; mi < 4; mi++) {
            const uint32_t ro = (uint32_t)(mi * 16 * PITCH * 2);
            uint32_t ah0, ah1, ah2, ah3, al0, al1, al2, al3;
            LDSM_X4(ah0, ah1, ah2, ah3, AhB + aRowB + ro);
            LDSM_X4(al0, al1, al2, al3, AlB + aRowB + ro);
#pragma unroll
            for (int nj = 0; nj < 4; nj++) {
                MMA_BF16(acc[mi][nj], ah0, ah1, ah2, ah3, bh[nj][0], bh[nj][1]);
                MMA_BF16(acc[mi][nj], ah0, ah1, ah2, ah3, bl[nj][0], bl[nj][1]);
                MMA_BF16(acc[mi][nj], al0, al1, al2, al3, bh[nj][0], bh[nj][1]);
            }
        }
        // no trailing sync: next iteration's top sync provides the ordering
    }

    // epilogue: add bias, write fp32 logits
#pragma unroll
    for (int mi = 0; mi < 4; mi++) {
#pragma unroll
        for (int nj = 0; nj < 4; nj++) {
            const int gr = bm * 128 + wm * 64 + mi * 16 + qr;
            const int gc = bn * 128 + wn * 32 + nj * 8 + 2 * qc;
            const float b0 = __ldg(&bias[gc]);
            const float b1 = __ldg(&bias[gc + 1]);
            float2 v0 = make_float2(acc[mi][nj][0] + b0, acc[mi][nj][1] + b1);
            float2 v1 = make_float2(acc[mi][nj][2] + b0, acc[mi][nj][3] + b1);
            *(float2*)&g_logits[(size_t)gr * GV + gc]       = v0;
            *(float2*)&g_logits[(size_t)(gr + 8) * GV + gc] = v1;
        }
    }
}

// ---------------------------------------------------------------------------
// Kernel 2: fused epilogue — REDUX-based argmaxes, softmax accumulation in
// registers, near-tie flagging, codebook gather. 64 rows/block, 8 warps.
// ---------------------------------------------------------------------------
__global__ __launch_bounds__(256)
void epilogue_kernel(const float* __restrict__ gumbel,   // [NROW, GV]
                     const float* __restrict__ codebook, // [GV, VD]
                     float* __restrict__ out)            // [NROW, 256]
{
    __shared__ float sProb[GV];
    __shared__ float sCnt[GV];
    __shared__ int   sIdx[64][2];

    const int tid  = threadIdx.x;
    const int warp = tid >> 5;
    const int lane = tid & 31;
    const int n0   = blockIdx.x * 64;

    for (int i = tid; i < GV; i += 256) { sProb[i] = 0.0f; sCnt[i] = 0.0f; }
    __syncthreads();

    float pacc[20];
#pragma unroll
    for (int i = 0; i < 20; i++) pacc[i] = 0.0f;

    for (int rr = 0; rr < 8; rr++) {
        const int n = n0 + warp * 8 + rr;
#pragma unroll
        for (int g = 0; g < NGROUP; g++) {
            const float2* Lg = (const float2*)(g_logits + (size_t)n * GV + g * VNUM);
            const float2* Gg = (const float2*)(gumbel   + (size_t)n * GV + g * VNUM);
            float lv[10];
            uint32_t kb = 0, kgb = 0, ksec = 0;
            uint32_t ib = 0xffffffffu, igb = 0xffffffffu;
#pragma unroll
            for (int j = 0; j < 5; j++) {
                const float2 l2 = Lg[lane + 32 * j];
                const float2 q2 = Gg[lane + 32 * j];
                const uint32_t v0 = 2 * lane + 64 * j;
                lv[2 * j]     = l2.x;
                lv[2 * j + 1] = l2.y;
                uint32_t k0 = fmono(l2.x);
                if (k0 > kb) { kb = k0; ib = v0; }
                uint32_t k1 = fmono(l2.y);
                if (k1 > kb) { kb = k1; ib = v0 + 1; }
                uint32_t q0 = fmono(l2.x + q2.x);
                if (q0 > kgb) { ksec = kgb; kgb = q0; igb = v0; }
                else if (q0 > ksec) ksec = q0;
                uint32_t q1 = fmono(l2.y + q2.y);
                if (q1 > kgb) { ksec = kgb; kgb = q1; igb = v0 + 1; }
                else if (q1 > ksec) ksec = q1;
            }
            const uint32_t kmax = __reduce_max_sync(0xffffffffu, kb);
            const uint32_t mi =
                __reduce_min_sync(0xffffffffu, (kb == kmax) ? ib : 0xffffffffu);
            const uint32_t gkmax = __reduce_max_sync(0xffffffffu, kgb);
            const uint32_t gmi =
                __reduce_min_sync(0xffffffffu, (kgb == gkmax) ? igb : 0xffffffffu);
            const uint32_t gsec = __reduce_max_sync(
                0xffffffffu, (kgb == gkmax && igb == gmi) ? ksec : kgb);

            const float mx = kinv(kmax);
            float ev[10];
            float s = 0.0f;
#pragma unroll
            for (int t = 0; t < 10; t++) { ev[t] = __expf(lv[t] - mx); s += ev[t]; }
#pragma unroll
            for (int off = 16; off; off >>= 1)
                s += __shfl_xor_sync(0xffffffffu, s, off);
            const float inv = 1.0f / s;
#pragma unroll
            for (int t = 0; t < 10; t++) pacc[g * 10 + t] += ev[t] * inv;

            if (lane == 0) {
                atomicAdd(&sCnt[g * VNUM + mi], 1.0f);
                sIdx[warp * 8 + rr][g] = (int)gmi;
                if (kinv(gkmax) - kinv(gsec) < REF_TAU) {
                    int pos = atomicAdd(&g_ref_cnt, 1);
                    if (pos < RCAP) g_ref_list[pos] = (n << 1) | g;
                }
            }
        }
    }
#pragma unroll
    for (int g = 0; g < NGROUP; g++)
#pragma unroll
        for (int j = 0; j < 5; j++) {
            atomicAdd(&sProb[g * VNUM + 2 * lane + 64 * j],     pacc[g * 10 + 2 * j]);
            atomicAdd(&sProb[g * VNUM + 2 * lane + 64 * j + 1], pacc[g * 10 + 2 * j + 1]);
        }
    __syncthreads();

    for (int i = tid; i < GV; i += 256) {
        atomicAdd(&g_prob[i], sProb[i]);
        atomicAdd(&g_cnt[i],  sCnt[i]);
    }

    // Output gather: 64 rows * 256 floats = 4096 float4
#pragma unroll
    for (int i = 0; i < 16; i++) {
        const int q   = tid + i * 256;
        const int row = q >> 6;
        const int f4  = q & 63;
        const int g   = f4 >> 5;
        const int idx = sIdx[row][g];
        const float4* src = (const float4*)(codebook + (size_t)(g * VNUM + idx) * VD)
                            + (f4 & 31);
        ((float4*)(out + (size_t)(n0 + row) * 256))[f4] = __ldg(src);
    }
}

// ---------------------------------------------------------------------------
// Kernel 2b: exact refinement of near-tie gumbel argmaxes.
// Two channels per warp-iteration (j, j+16) for 2x memory-level parallelism;
// index-aware compares preserve first-index tie-break.
// Block 0 additionally finalizes the perplexity scalars.
// ---------------------------------------------------------------------------
__global__ __launch_bounds__(320)
void refine_kernel(const float* __restrict__ x,
                   const float* __restrict__ W,
                   const float* __restrict__ bias,
                   const float* __restrict__ gumbel,
                   const float* __restrict__ codebook,
                   float* __restrict__ out, int out_size)
{
    __shared__ float xs[KDIM];
    __shared__ float sBest[10];
    __shared__ int   sBi[10];
    __shared__ int   sFinal;
    __shared__ float wp[20], wh[20];

    const int tid = threadIdx.x, warp = tid >> 5, lane = tid & 31;

    // Block 0: finalize perplexity scalars (two passes of 320 threads)
    if (blockIdx.x == 0) {
#pragma unroll
        for (int pass = 0; pass < 2; pass++) {
            const int idx = tid + pass * 320;
            const float p = g_prob[idx] * (1.0f / (float)NROW);
            const float h = g_cnt[idx]  * (1.0f / (float)NROW);
            float pt = p * logf(p + EPSQ);
            float ht = h * logf(h + EPSQ);
#pragma unroll
            for (int off = 16; off; off >>= 1) {
                pt += __shfl_xor_sync(0xffffffffu, pt, off);
                ht += __shfl_xor_sync(0xffffffffu, ht, off);
            }
            if (lane == 0) { wp[pass * 10 + warp] = pt; wh[pass * 10 + warp] = ht; }
        }
        __syncthreads();
        if (tid == 0) {
            // pass p covers bins [320p, 320p+320) => pass0 = group 0, pass1 = group 1
            float p0 = 0.f, h0 = 0.f, p1 = 0.f, h1 = 0.f;
            for (int w = 0; w < 10; w++)  { p0 += wp[w]; h0 += wh[w]; }
            for (int w = 10; w < 20; w++) { p1 += wp[w]; h1 += wh[w]; }
            const float code_pplx = expf(-h0) + expf(-h1);
            const float prob_pplx = expf(-p0) + expf(-p1);
            if (out_size > OUT_MAIN)     out[OUT_MAIN]     = code_pplx;
            if (out_size > OUT_MAIN + 1) out[OUT_MAIN + 1] = prob_pplx;
        }
        __syncthreads();
    }

    int cnt = g_ref_cnt; if (cnt > RCAP) cnt = RCAP;
    const int e = blockIdx.x;
    if (e >= cnt) return;
    const int ng = g_ref_list[e];
    const int n  = ng >> 1;
    const int g  = ng & 1;

    for (int i = tid; i < KDIM; i += 320) xs[i] = x[(size_t)n * KDIM + i];
    __syncthreads();

    float best = -INFINITY; int bi = VNUM;
    const float4* xr4 = (const float4*)xs;
    for (int j = 0; j < 16; j++) {
        const int c0 = warp * 32 + j;
        const int c1 = c0 + 16;
        const float4* wr0 = (const float4*)(W + (size_t)(g * VNUM + c0) * KDIM);
        const float4* wr1 = (const float4*)(W + (size_t)(g * VNUM + c1) * KDIM);
        float s0 = 0.0f, s1 = 0.0f;
#pragma unroll
        for (int i = 0; i < 4; i++) {
            const float4 x4 = xr4[lane + 32 * i];
            const float4 w0 = __ldg(&wr0[lane + 32 * i]);
            const float4 w1 = __ldg(&wr1[lane + 32 * i]);
            s0 = fmaf(w0.x, x4.x, s0); s0 = fmaf(w0.y, x4.y, s0);
            s0 = fmaf(w0.z, x4.z, s0); s0 = fmaf(w0.w, x4.w, s0);
            s1 = fmaf(w1.x, x4.x, s1); s1 = fmaf(w1.y, x4.y, s1);
            s1 = fmaf(w1.z, x4.z, s1); s1 = fmaf(w1.w, x4.w, s1);
        }
#pragma unroll
        for (int off = 16; off; off >>= 1) {
            s0 += __shfl_xor_sync(0xffffffffu, s0, off);
            s1 += __shfl_xor_sync(0xffffffffu, s1, off);
        }
        if (lane == 0) {
            const float ge0 = s0 + bias[g * VNUM + c0]
                            + gumbel[(size_t)n * GV + g * VNUM + c0];
            const float ge1 = s1 + bias[g * VNUM + c1]
                            + gumbel[(size_t)n * GV + g * VNUM + c1];
            if (ge0 > best || (ge0 == best && c0 < bi)) { best = ge0; bi = c0; }
            if (ge1 > best || (ge1 == best && c1 < bi)) { best = ge1; bi = c1; }
        }
    }
    if (lane == 0) { sBest[warp] = best; sBi[warp] = bi; }
    __syncthreads();
    if (tid == 0) {
        float b = sBest[0]; int ix = sBi[0];
        for (int w = 1; w < 10; w++)
            if (sBest[w] > b || (sBest[w] == b && sBi[w] < ix)) { b = sBest[w]; ix = sBi[w]; }
        sFinal = ix;
    }
    __syncthreads();
    const int idx = sFinal;
    if (tid < VD)
        out[(size_t)n * 256 + g * VD + tid] =
            codebook[(size_t)(g * VNUM + idx) * VD + tid];
}

// ---------------------------------------------------------------------------
extern "C" void kernel_launch(void* const* d_in, const int* in_sizes, int n_in,
                              void* d_out, int out_size)
{
    const float* x    = (const float*)d_in[0];   // [16,1536,512]
    const float* W    = (const float*)d_in[1];   // [640,512]
    const float* bias = (const float*)d_in[2];   // [640]
    const float* cb   = (const float*)d_in[3];   // [1,640,128]
    const float* gum  = (const float*)d_in[4];   // [24576,2,320]
    float* out = (float*)d_out;

    convert_kernel<<<(NX8 + NW8 + 255) / 256, 256>>>(x, W);

    dim3 grid(GV / 128, NROW / 128);             // (5, 192)
    gemm3_kernel<<<grid, 256>>>(bias);

    epilogue_kernel<<<NROW / 64, 256>>>(gum, cb, out);

    refine_kernel<<<RCAP, 320>>>(x, W, bias, gum, cb, out, out_size);
}

// round 17
// speedup vs baseline: 1.0308x; 1.0308x over previous
#include <cuda_runtime.h>
#include <cuda_bf16.h>
#include <math.h>
#include <stdint.h>

// Problem constants (fixed shapes)
#define NROW   24576          // B*T
#define KDIM   512            // DIM
#define GV     640            // G*V
#define VNUM   320            // V per group
#define VD     128            // var_dim per group
#define NGROUP 2
#define OUT_MAIN (NROW * (NGROUP * VD))   // 24576*256
#define EPSQ   1e-7f
#define RCAP   4096           // refinement list capacity
#define RGRID  1024           // refine grid (50-sigma bound on flag count)
#define REF_TAU 0.005f        // near-tie threshold for gumbel argmax

// Scratch (static device globals; no runtime allocation)
__device__ float g_logits[(size_t)NROW * GV];
__device__ float g_prob[GV];
__device__ float g_cnt[GV];
__device__ int   g_ref_cnt;
__device__ int   g_ref_list[RCAP];
__device__ __nv_bfloat16 g_xh[(size_t)NROW * KDIM];
__device__ __nv_bfloat16 g_xl[(size_t)NROW * KDIM];
__device__ __nv_bfloat16 g_wh[(size_t)GV * KDIM];
__device__ __nv_bfloat16 g_wl[(size_t)GV * KDIM];

// monotonic float<->uint key (no NaNs in this data)
__device__ __forceinline__ uint32_t fmono(float f) {
    uint32_t b = __float_as_uint(f);
    return (b & 0x80000000u) ? ~b : (b | 0x80000000u);
}
__device__ __forceinline__ float kinv(uint32_t k) {
    return __uint_as_float((k & 0x80000000u) ? (k ^ 0x80000000u) : ~k);
}

// ---------------------------------------------------------------------------
// Convert kernel: fp32 -> (bf16 hi, bf16 lo) split, 32B of input per thread,
// full 16B stores to each of hi/lo. Block 0 also zeroes the accumulators.
// ---------------------------------------------------------------------------
__device__ __forceinline__ void split4(float4 v, uint2& ph, uint2& pl) {
    __nv_bfloat16 h0 = __float2bfloat16_rn(v.x);
    __nv_bfloat16 h1 = __float2bfloat16_rn(v.y);
    __nv_bfloat16 h2 = __float2bfloat16_rn(v.z);
    __nv_bfloat16 h3 = __float2bfloat16_rn(v.w);
    __nv_bfloat16 l0 = __float2bfloat16_rn(v.x - __bfloat162float(h0));
    __nv_bfloat16 l1 = __float2bfloat16_rn(v.y - __bfloat162float(h1));
    __nv_bfloat16 l2 = __float2bfloat16_rn(v.z - __bfloat162float(h2));
    __nv_bfloat16 l3 = __float2bfloat16_rn(v.w - __bfloat162float(h3));
    ph.x = ((uint32_t)__bfloat16_as_ushort(h1) << 16) | __bfloat16_as_ushort(h0);
    ph.y = ((uint32_t)__bfloat16_as_ushort(h3) << 16) | __bfloat16_as_ushort(h2);
    pl.x = ((uint32_t)__bfloat16_as_ushort(l1) << 16) | __bfloat16_as_ushort(l0);
    pl.y = ((uint32_t)__bfloat16_as_ushort(l3) << 16) | __bfloat16_as_ushort(l2);
}

__device__ __forceinline__ void split8(const float4* src8, uint4& ph, uint4& pl) {
    uint2 ph0, pl0, ph1, pl1;
    split4(src8[0], ph0, pl0);
    split4(src8[1], ph1, pl1);
    ph = make_uint4(ph0.x, ph0.y, ph1.x, ph1.y);
    pl = make_uint4(pl0.x, pl0.y, pl1.x, pl1.y);
}

#define NX8 (NROW * KDIM / 8)   // 1572864 float4-pairs of x
#define NW8 (GV * KDIM / 8)     // 40960 float4-pairs of W

__global__ void convert_kernel(const float* __restrict__ x,
                               const float* __restrict__ W) {
    if (blockIdx.x == 0) {
        for (int t = threadIdx.x; t < GV; t += blockDim.x) {
            g_prob[t] = 0.0f; g_cnt[t] = 0.0f;
        }
        if (threadIdx.x == 0) g_ref_cnt = 0;
    }
    int i = blockIdx.x * blockDim.x + threadIdx.x;
    uint4 ph, pl;
    if (i < NX8) {
        split8((const float4*)x + 2 * (size_t)i, ph, pl);
        ((uint4*)g_xh)[i] = ph;
        ((uint4*)g_xl)[i] = pl;
    } else {
        int j = i - NX8;
        if (j < NW8) {
            split8((const float4*)W + 2 * (size_t)j, ph, pl);
            ((uint4*)g_wh)[j] = ph;
            ((uint4*)g_wl)[j] = pl;
        }
    }
}

// ---------------------------------------------------------------------------
// Kernel 1: 3-term split-bf16 GEMM via mma.sync.m16n8k16 + cp.async pipeline
// + ldmatrix.x4 (exact R13 mainloop — register knife-edge, do not add state).
// 128x128 tiles, k-tile 16, 2-stage, 256 threads (8 warps as 2m x 4n).
// Static 48KB smem. One __syncthreads per k-iteration.
// ---------------------------------------------------------------------------
#define KT    16
#define PITCH 24   // halves per row (48B; LDSM rows land on distinct bank groups)

#define MMA_BF16(d, a0, a1, a2, a3, b0, b1)                                  \
    asm volatile("mma.sync.aligned.m16n8k16.row.col.f32.bf16.bf16.f32 "      \
                 "{%0,%1,%2,%3}, {%4,%5,%6,%7}, {%8,%9}, {%0,%1,%2,%3};"     \
                 : "+f"(d[0]), "+f"(d[1]), "+f"(d[2]), "+f"(d[3])            \
                 : "r"(a0), "r"(a1), "r"(a2), "r"(a3), "r"(b0), "r"(b1))

#define CP_ASYNC16(saddr, gptr)                                              \
    asm volatile("cp.async.cg.shared.global [%0], [%1], 16;"                 \
                 :: "r"(saddr), "l"(gptr))

#define LDSM_X4(d0, d1, d2, d3, saddr)                                       \
    asm volatile("ldmatrix.sync.aligned.m8n8.x4.shared.b16 {%0,%1,%2,%3}, [%4];" \
                 : "=r"(d0), "=r"(d1), "=r"(d2), "=r"(d3) : "r"(saddr))

__global__ __launch_bounds__(256, 2)
void gemm3_kernel(const float* __restrict__ bias)
{
    // [stage][src][128*PITCH] : src 0=Ah 1=Al 2=Bh 3=Bl   (49152 bytes)
    __shared__ __nv_bfloat16 sm[2][4][128 * PITCH];

    const int tid  = threadIdx.x;
    const int bn   = blockIdx.x;          // 0..4
    const int bm   = blockIdx.y;          // 0..191
    const int warp = tid >> 5, lane = tid & 31;
    const int wm   = warp & 1;            // m offset 64*wm
    const int wn   = warp >> 1;           // n offset 32*wn
    const int qr   = lane >> 2, qc = lane & 3;

    // cp.async mapping: thread covers one 16B chunk per source per stage
    const int lrow = tid >> 1;            // 0..127
    const int lcol = (tid & 1) * 8;       // 0 or 8 (halves)
    const __nv_bfloat16* pAh = g_xh + (size_t)(bm * 128 + lrow) * KDIM + lcol;
    const __nv_bfloat16* pAl = g_xl + (size_t)(bm * 128 + lrow) * KDIM + lcol;
    const __nv_bfloat16* pBh = g_wh + (size_t)(bn * 128 + lrow) * KDIM + lcol;
    const __nv_bfloat16* pBl = g_wl + (size_t)(bn * 128 + lrow) * KDIM + lcol;

    uint32_t sbase = (uint32_t)__cvta_generic_to_shared(&sm[0][0][0]);
    const uint32_t soff = (uint32_t)(lrow * PITCH + lcol) * 2;
    const uint32_t stg  = 4u * 128u * PITCH * 2u;   // bytes per stage
    const uint32_t srcb = 128u * PITCH * 2u;        // bytes per source

    // ldmatrix lane addressing
    const int lg = lane >> 3;             // 0..3 (8-lane group)
    const int lr = lane & 7;              // row within group
    const uint32_t aRowB = (uint32_t)(wm * 64 + ((lg & 1) << 3) + lr) * (PITCH * 2)
                         + ((uint32_t)(lg >> 1) << 4);
    const uint32_t bRowB = (uint32_t)(wn * 32 + ((lg >> 1) << 3) + lr) * (PITCH * 2)
                         + ((uint32_t)(lg & 1) << 4);

    float acc[4][4][4];
#pragma unroll
    for (int mi = 0; mi < 4; mi++)
#pragma unroll
        for (int nj = 0; nj < 4; nj++)
#pragma unroll
            for (int r = 0; r < 4; r++) acc[mi][nj][r] = 0.0f;

    const int NK = KDIM / KT;   // 32

    // issue stage 0
    {
        const uint32_t d = sbase + soff;
        CP_ASYNC16(d + 0 * srcb, pAh);
        CP_ASYNC16(d + 1 * srcb, pAl);
        CP_ASYNC16(d + 2 * srcb, pBh);
        CP_ASYNC16(d + 3 * srcb, pBl);
        asm volatile("cp.async.commit_group;");
    }

    for (int kt = 0; kt < NK; kt++) {
        const int s = kt & 1;
        asm volatile("cp.async.wait_group 0;");
        __syncthreads();   // stage s visible; all warps done with stage s^1

        if (kt + 1 < NK) {
            const int ko = (kt + 1) * KT;
            const uint32_t d = sbase + (s ^ 1) * stg + soff;
            CP_ASYNC16(d + 0 * srcb, pAh + ko);
            CP_ASYNC16(d + 1 * srcb, pAl + ko);
            CP_ASYNC16(d + 2 * srcb, pBh + ko);
            CP_ASYNC16(d + 3 * srcb, pBl + ko);
            asm volatile("cp.async.commit_group;");
        }

        const uint32_t AhB = sbase + s * stg + 0 * srcb;
        const uint32_t AlB = sbase + s * stg + 1 * srcb;
        const uint32_t BhB = sbase + s * stg + 2 * srcb;
        const uint32_t BlB = sbase + s * stg + 3 * srcb;

        // B fragments for the whole k-tile (one KT=16 slice)
        uint32_t bh[4][2], bl[4][2];
#pragma unroll
        for (int p = 0; p < 2; p++) {
            const uint32_t ro = (uint32_t)(p * 16 * PITCH * 2);
            LDSM_X4(bh[2 * p][0], bh[2 * p][1], bh[2 * p + 1][0], bh[2 * p + 1][1],
                    BhB + bRowB + ro);
            LDSM_X4(bl[2 * p][0], bl[2 * p][1], bl[2 * p + 1][0], bl[2 * p + 1][1],
                    BlB + bRowB + ro);
        }
#pragma unroll
        for (int mi = 0; mi < 4; mi++) {
            const uint32_t ro = (uint32_t)(mi * 16 * PITCH * 2);
            uint32_t ah0, ah1, ah2, ah3, al0, al1, al2, al3;
            LDSM_X4(ah0, ah1, ah2, ah3, AhB + aRowB + ro);
            LDSM_X4(al0, al1, al2, al3, AlB + aRowB + ro);
#pragma unroll
            for (int nj = 0; nj < 4; nj++) {
                MMA_BF16(acc[mi][nj], ah0, ah1, ah2, ah3, bh[nj][0], bh[nj][1]);
                MMA_BF16(acc[mi][nj], ah0, ah1, ah2, ah3, bl[nj][0], bl[nj][1]);
                MMA_BF16(acc[mi][nj], al0, al1, al2, al3, bh[nj][0], bh[nj][1]);
            }
        }
        // no trailing sync: next iteration's top sync provides the ordering
    }

    // epilogue: add bias, write fp32 logits
#pragma unroll
    for (int mi = 0; mi < 4; mi++) {
#pragma unroll
        for (int nj = 0; nj < 4; nj++) {
            const int gr = bm * 128 + wm * 64 + mi * 16 + qr;
            const int gc = bn * 128 + wn * 32 + nj * 8 + 2 * qc;
            const float b0 = __ldg(&bias[gc]);
            const float b1 = __ldg(&bias[gc + 1]);
            float2 v0 = make_float2(acc[mi][nj][0] + b0, acc[mi][nj][1] + b1);
            float2 v1 = make_float2(acc[mi][nj][2] + b0, acc[mi][nj][3] + b1);
            *(float2*)&g_logits[(size_t)gr * GV + gc]       = v0;
            *(float2*)&g_logits[(size_t)(gr + 8) * GV + gc] = v1;
        }
    }
}

// ---------------------------------------------------------------------------
// Kernel 2: fused epilogue — REDUX-based argmaxes, softmax accumulation in
// registers, near-tie flagging, codebook gather. 64 rows/block, 8 warps.
// ---------------------------------------------------------------------------
__global__ __launch_bounds__(256)
void epilogue_kernel(const float* __restrict__ gumbel,   // [NROW, GV]
                     const float* __restrict__ codebook, // [GV, VD]
                     float* __restrict__ out)            // [NROW, 256]
{
    __shared__ float sProb[GV];
    __shared__ float sCnt[GV];
    __shared__ int   sIdx[64][2];

    const int tid  = threadIdx.x;
    const int warp = tid >> 5;
    const int lane = tid & 31;
    const int n0   = blockIdx.x * 64;

    for (int i = tid; i < GV; i += 256) { sProb[i] = 0.0f; sCnt[i] = 0.0f; }
    __syncthreads();

    float pacc[20];
#pragma unroll
    for (int i = 0; i < 20; i++) pacc[i] = 0.0f;

    for (int rr = 0; rr < 8; rr++) {
        const int n = n0 + warp * 8 + rr;
#pragma unroll
        for (int g = 0; g < NGROUP; g++) {
            const float2* Lg = (const float2*)(g_logits + (size_t)n * GV + g * VNUM);
            const float2* Gg = (const float2*)(gumbel   + (size_t)n * GV + g * VNUM);
            float lv[10];
            uint32_t kb = 0, kgb = 0, ksec = 0;
            uint32_t ib = 0xffffffffu, igb = 0xffffffffu;
#pragma unroll
            for (int j = 0; j < 5; j++) {
                const float2 l2 = Lg[lane + 32 * j];
                const float2 q2 = Gg[lane + 32 * j];
                const uint32_t v0 = 2 * lane + 64 * j;
                lv[2 * j]     = l2.x;
                lv[2 * j + 1] = l2.y;
                uint32_t k0 = fmono(l2.x);
                if (k0 > kb) { kb = k0; ib = v0; }
                uint32_t k1 = fmono(l2.y);
                if (k1 > kb) { kb = k1; ib = v0 + 1; }
                uint32_t q0 = fmono(l2.x + q2.x);
                if (q0 > kgb) { ksec = kgb; kgb = q0; igb = v0; }
                else if (q0 > ksec) ksec = q0;
                uint32_t q1 = fmono(l2.y + q2.y);
                if (q1 > kgb) { ksec = kgb; kgb = q1; igb = v0 + 1; }
                else if (q1 > ksec) ksec = q1;
            }
            const uint32_t kmax = __reduce_max_sync(0xffffffffu, kb);
            const uint32_t mi =
                __reduce_min_sync(0xffffffffu, (kb == kmax) ? ib : 0xffffffffu);
            const uint32_t gkmax = __reduce_max_sync(0xffffffffu, kgb);
            const uint32_t gmi =
                __reduce_min_sync(0xffffffffu, (kgb == gkmax) ? igb : 0xffffffffu);
            const uint32_t gsec = __reduce_max_sync(
                0xffffffffu, (kgb == gkmax && igb == gmi) ? ksec : kgb);

            const float mx = kinv(kmax);
            float ev[10];
            float s = 0.0f;
#pragma unroll
            for (int t = 0; t < 10; t++) { ev[t] = __expf(lv[t] - mx); s += ev[t]; }
#pragma unroll
            for (int off = 16; off; off >>= 1)
                s += __shfl_xor_sync(0xffffffffu, s, off);
            const float inv = 1.0f / s;
#pragma unroll
            for (int t = 0; t < 10; t++) pacc[g * 10 + t] += ev[t] * inv;

            if (lane == 0) {
                atomicAdd(&sCnt[g * VNUM + mi], 1.0f);
                sIdx[warp * 8 + rr][g] = (int)gmi;
                if (kinv(gkmax) - kinv(gsec) < REF_TAU) {
                    int pos = atomicAdd(&g_ref_cnt, 1);
                    if (pos < RCAP) g_ref_list[pos] = (n << 1) | g;
                }
            }
        }
    }
#pragma unroll
    for (int g = 0; g < NGROUP; g++)
#pragma unroll
        for (int j = 0; j < 5; j++) {
            atomicAdd(&sProb[g * VNUM + 2 * lane + 64 * j],     pacc[g * 10 + 2 * j]);
            atomicAdd(&sProb[g * VNUM + 2 * lane + 64 * j + 1], pacc[g * 10 + 2 * j + 1]);
        }
    __syncthreads();

    for (int i = tid; i < GV; i += 256) {
        atomicAdd(&g_prob[i], sProb[i]);
        atomicAdd(&g_cnt[i],  sCnt[i]);
    }

    // Output gather: 64 rows * 256 floats = 4096 float4
#pragma unroll
    for (int i = 0; i < 16; i++) {
        const int q   = tid + i * 256;
        const int row = q >> 6;
        const int f4  = q & 63;
        const int g   = f4 >> 5;
        const int idx = sIdx[row][g];
        const float4* src = (const float4*)(codebook + (size_t)(g * VNUM + idx) * VD)
                            + (f4 & 31);
        ((float4*)(out + (size_t)(n0 + row) * 256))[f4] = __ldg(src);
    }
}

// ---------------------------------------------------------------------------
// Kernel 2b: exact refinement of near-tie gumbel argmaxes (R15 form).
// RGRID=1024 blocks (50-sigma bound on expected ~245 flags).
// Block 0 additionally finalizes the perplexity scalars.
// ---------------------------------------------------------------------------
__global__ __launch_bounds__(320)
void refine_kernel(const float* __restrict__ x,
                   const float* __restrict__ W,
                   const float* __restrict__ bias,
                   const float* __restrict__ gumbel,
                   const float* __restrict__ codebook,
                   float* __restrict__ out, int out_size)
{
    __shared__ float xs[KDIM];
    __shared__ float sBest[10];
    __shared__ int   sBi[10];
    __shared__ int   sFinal;
    __shared__ float wp[20], wh[20];

    const int tid = threadIdx.x, warp = tid >> 5, lane = tid & 31;

    // Block 0: finalize perplexity scalars (two passes of 320 threads)
    if (blockIdx.x == 0) {
#pragma unroll
        for (int pass = 0; pass < 2; pass++) {
            const int idx = tid + pass * 320;
            const float p = g_prob[idx] * (1.0f / (float)NROW);
            const float h = g_cnt[idx]  * (1.0f / (float)NROW);
            float pt = p * logf(p + EPSQ);
            float ht = h * logf(h + EPSQ);
#pragma unroll
            for (int off = 16; off; off >>= 1) {
                pt += __shfl_xor_sync(0xffffffffu, pt, off);
                ht += __shfl_xor_sync(0xffffffffu, ht, off);
            }
            if (lane == 0) { wp[pass * 10 + warp] = pt; wh[pass * 10 + warp] = ht; }
        }
        __syncthreads();
        if (tid == 0) {
            // pass p covers bins [320p, 320p+320) => pass0 = group 0, pass1 = group 1
            float p0 = 0.f, h0 = 0.f, p1 = 0.f, h1 = 0.f;
            for (int w = 0; w < 10; w++)  { p0 += wp[w]; h0 += wh[w]; }
            for (int w = 10; w < 20; w++) { p1 += wp[w]; h1 += wh[w]; }
            const float code_pplx = expf(-h0) + expf(-h1);
            const float prob_pplx = expf(-p0) + expf(-p1);
            if (out_size > OUT_MAIN)     out[OUT_MAIN]     = code_pplx;
            if (out_size > OUT_MAIN + 1) out[OUT_MAIN + 1] = prob_pplx;
        }
        __syncthreads();
    }

    int cnt = g_ref_cnt; if (cnt > RCAP) cnt = RCAP;
    const int e = blockIdx.x;
    if (e >= cnt) return;
    const int ng = g_ref_list[e];
    const int n  = ng >> 1;
    const int g  = ng & 1;

    for (int i = tid; i < KDIM; i += 320) xs[i] = x[(size_t)n * KDIM + i];
    __syncthreads();

    float best = -INFINITY; int bi = -1;
    for (int j = 0; j < 32; j++) {
        const int c = warp * 32 + j;
        const float4* wr = (const float4*)(W + (size_t)(g * VNUM + c) * KDIM);
        const float4* xr4 = (const float4*)xs;
        float s = 0.0f;
#pragma unroll
        for (int i = 0; i < 4; i++) {
            const float4 w4 = __ldg(&wr[lane + 32 * i]);
            const float4 x4 = xr4[lane + 32 * i];
            s = fmaf(w4.x, x4.x, s);
            s = fmaf(w4.y, x4.y, s);
            s = fmaf(w4.z, x4.z, s);
            s = fmaf(w4.w, x4.w, s);
        }
#pragma unroll
        for (int off = 16; off; off >>= 1)
            s += __shfl_xor_sync(0xffffffffu, s, off);
        if (lane == 0) {
            const float ge = s + bias[g * VNUM + c]
                           + gumbel[(size_t)n * GV + g * VNUM + c];
            if (ge > best) { best = ge; bi = c; }   // strict >: first index
        }
    }
    if (lane == 0) { sBest[warp] = best; sBi[warp] = bi; }
    __syncthreads();
    if (tid == 0) {
        float b = sBest[0]; int ix = sBi[0];
        for (int w = 1; w < 10; w++)            // ascending warps: first index
            if (sBest[w] > b) { b = sBest[w]; ix = sBi[w]; }
        sFinal = ix;
    }
    __syncthreads();
    const int idx = sFinal;
    if (tid < VD)
        out[(size_t)n * 256 + g * VD + tid] =
            codebook[(size_t)(g * VNUM + idx) * VD + tid];
}

// ---------------------------------------------------------------------------
extern "C" void kernel_launch(void* const* d_in, const int* in_sizes, int n_in,
                              void* d_out, int out_size)
{
    const float* x    = (const float*)d_in[0];   // [16,1536,512]
    const float* W    = (const float*)d_in[1];   // [640,512]
    const float* bias = (const float*)d_in[2];   // [640]
    const float* cb   = (const float*)d_in[3];   // [1,640,128]
    const float* gum  = (const float*)d_in[4];   // [24576,2,320]
    float* out = (float*)d_out;

    convert_kernel<<<(NX8 + NW8 + 255) / 256, 256>>>(x, W);

    dim3 grid(GV / 128, NROW / 128);             // (5, 192)
    gemm3_kernel<<<grid, 256>>>(bias);

    epilogue_kernel<<<NROW / 64, 256>>>(gum, cb, out);

    refine_kernel<<<RGRID, 320>>>(x, W, bias, gum, cb, out, out_size);
}